// round 10
// baseline (speedup 1.0000x reference)
#include <cuda_runtime.h>
#include <cuda_bf16.h>
#include <cuda_fp16.h>
#include <cstdint>

// Problem shape: N=40000 nodes, F_in=256, F_out=128, E=640000 edges.
static constexpr int MAXN = 40000;
static constexpr int MAXE = 640000;

// Scratch (allocation-free rule: __device__ globals)
__device__ int    g_is64;               // 1 if edge_index is int64, 0 if int32
__device__ __align__(16) int g_cnt[MAXN];   // in-degree histogram
__device__ int    g_rowptr[MAXN + 1];   // CSR row pointers (by dst)
__device__ float  g_dinv[MAXN];         // rsqrt(deg+1)
__device__ int    g_srcid[MAXE];        // CSR column (source node) ids
__device__ unsigned g_sd[MAXE];         // packed (d<<16)|s per edge
__device__ unsigned g_pos[MAXE];        // slot within dst bucket per edge
__device__ __align__(16) __half g_xwh[MAXN * 128];  // fp16 dinv[i]*(x@W)[i]
// W^T image: [n=128][k=256] fp16
__device__ __align__(16) __half g_wh[128 * 256];

// ---------------------------------------------------------------------------
__device__ __forceinline__ uint32_t smem_u32(const void* p) {
    uint32_t a;
    asm("{ .reg .u64 t; cvta.to.shared.u64 t, %1; cvt.u32.u64 %0, t; }" : "=r"(a) : "l"(p));
    return a;
}
#define LDSM_X4(r0, r1, r2, r3, adr)                                              \
    asm volatile("ldmatrix.sync.aligned.m8n8.x4.shared.b16 {%0,%1,%2,%3}, [%4];"  \
                 : "=r"(r0), "=r"(r1), "=r"(r2), "=r"(r3) : "r"(adr))
#define MMA_F16(c, a, b)                                                          \
    asm volatile("mma.sync.aligned.m16n8k16.row.col.f32.f16.f16.f32 "             \
                 "{%0,%1,%2,%3}, {%4,%5,%6,%7}, {%8,%9}, {%0,%1,%2,%3};"          \
                 : "+f"((c)[0]), "+f"((c)[1]), "+f"((c)[2]), "+f"((c)[3])         \
                 : "r"((a)[0]), "r"((a)[1]), "r"((a)[2]), "r"((a)[3]),            \
                   "r"((b)[0]), "r"((b)[1]))
#define CP_ASYNC16(dst, src)                                                      \
    asm volatile("cp.async.cg.shared.global [%0], [%1], 16;"                      \
                 :: "r"(dst), "l"(src) : "memory")
#define CP_COMMIT() asm volatile("cp.async.commit_group;" ::: "memory")
#define CP_WAIT0()  asm volatile("cp.async.wait_group 0;" ::: "memory")

// ---------------------------------------------------------------------------
// 1) init: zero counters; block 0 probes index dtype; first 32768 threads
//    build the W^T fp16 image.
__global__ void init_kernel(const int* __restrict__ ei32,
                            const float* __restrict__ W, int N) {
    int i = blockIdx.x * blockDim.x + threadIdx.x;
    if (i < N) g_cnt[i] = 0;
    if (i < 128 * 256) {
        int k = i & 255;
        int n = i >> 8;
        g_wh[n * 256 + k] = __float2half_rn(W[(size_t)k * 128 + n]);
    }
    if (blockIdx.x == 0) {
        __shared__ int red[8];
        int tid = threadIdx.x;
        int acc = 0;
        for (int k = tid; k < 1024; k += 256)
            acc |= ei32[2 * k + 1];              // int64 high halves
        #pragma unroll
        for (int off = 16; off > 0; off >>= 1)
            acc |= __shfl_down_sync(0xFFFFFFFFu, acc, off);
        if ((tid & 31) == 0) red[tid >> 5] = acc;
        __syncthreads();
        if (tid == 0) {
            int r = 0;
            #pragma unroll
            for (int w = 0; w < 8; w++) r |= red[w];
            g_is64 = (r == 0) ? 1 : 0;
        }
    }
}

__device__ __forceinline__ int load_idx(const void* ei, long long i, int is64) {
    if (is64) return (int)((const long long*)ei)[i];
    return ((const int*)ei)[i];
}

// 2) histogram of dst + record packed (d,s) and bucket slot per edge
__global__ void count_kernel(const void* __restrict__ ei, int E, int N) {
    int e = blockIdx.x * blockDim.x + threadIdx.x;
    if (e < E) {
        int is64 = g_is64;
        unsigned d = (unsigned)load_idx(ei, (long long)E + e, is64);
        unsigned s = (unsigned)load_idx(ei, e, is64);
        if (d < (unsigned)N && s < (unsigned)N) {
            unsigned pos = (unsigned)atomicAdd(&g_cnt[d], 1);
            g_pos[e] = pos;
            g_sd[e]  = (d << 16) | s;            // both < 65536
        } else {
            g_sd[e] = 0xFFFFFFFFu;               // sentinel: skip
        }
    }
}

// 3) exclusive scan of g_cnt -> g_rowptr; fused dinv. 4 elements/thread.
__global__ void __launch_bounds__(1024) scan_kernel(int N) {
    __shared__ int shw[32];
    __shared__ int carry;
    int tid = threadIdx.x, lane = tid & 31, warp = tid >> 5;
    if (tid == 0) { carry = 0; g_rowptr[0] = 0; }
    __syncthreads();
    for (int base = 0; base < N; base += 4096) {
        int i0 = base + tid * 4;
        int v[4];
        if (i0 + 3 < N) {
            int4 q = *(const int4*)&g_cnt[i0];
            v[0] = q.x; v[1] = q.y; v[2] = q.z; v[3] = q.w;
        } else {
            #pragma unroll
            for (int j = 0; j < 4; j++) v[j] = (i0 + j < N) ? g_cnt[i0 + j] : 0;
        }
        int tsum = v[0] + v[1] + v[2] + v[3];
        int s = tsum;
        #pragma unroll
        for (int off = 1; off < 32; off <<= 1) {
            int t = __shfl_up_sync(0xFFFFFFFFu, s, off);
            if (lane >= off) s += t;
        }
        if (lane == 31) shw[warp] = s;
        __syncthreads();
        if (warp == 0) {
            int ws = shw[lane];
            #pragma unroll
            for (int off = 1; off < 32; off <<= 1) {
                int t = __shfl_up_sync(0xFFFFFFFFu, ws, off);
                if (lane >= off) ws += t;
            }
            shw[lane] = ws;
        }
        __syncthreads();
        int run = (s - tsum) + (warp > 0 ? shw[warp - 1] : 0) + carry;
        #pragma unroll
        for (int j = 0; j < 4; j++) {
            run += v[j];
            if (i0 + j < N) {
                g_rowptr[i0 + j + 1] = run;
                g_dinv[i0 + j] = rsqrtf((float)v[j] + 1.0f);
            }
        }
        __syncthreads();
        if (tid == 0) carry += shw[31];
        __syncthreads();
    }
}

// 4) scatter (atomic-free): srcid[rowptr[d] + pos] = s
__global__ void scatter_kernel(int E, int N) {
    int e = blockIdx.x * blockDim.x + threadIdx.x;
    if (e < E) {
        unsigned sd = g_sd[e];
        unsigned d  = sd >> 16;
        if (d < (unsigned)N) {
            unsigned s = sd & 0xFFFFu;
            g_srcid[g_rowptr[d] + g_pos[e]] = (int)s;
        }
    }
}

// ---------------------------------------------------------------------------
// 5) GEMM via mma.sync fp16 with cp.async pipeline:
//    xwh[i,:] = fp16( dinv[i] * (x[i,:] @ W) )
//    CTA 128Mx128N, 16 warps (4Mx4N), warp 32Mx32N; K chunks of 64.
//    Staging buffer (fp32 x chunk) + double-buffered B, cp.async overlapped.
static constexpr int ST_HSTRIDE = 2052;               // floats per h-block (+4 pad)
static constexpr int SM_ST  = 0;                      // 4 * 2052 * 4 = 32832 B
static constexpr int SM_AH  = 32832;                  // fp16 A image, 128*144 B
static constexpr int SM_B0  = SM_AH + 18432;          // 51264
static constexpr int SM_B1  = SM_B0 + 18432;          // 69696
static constexpr int SM_TOT = SM_B1 + 18432;          // 88128 B (2 CTAs/SM)

__global__ void __launch_bounds__(512, 2)
gemm_kernel(const float* __restrict__ x, int N) {
    extern __shared__ unsigned char smc[];
    const uint32_t sm = smem_u32(smc);
    const int tid  = threadIdx.x;
    const int lane = tid & 31;
    const int wid  = tid >> 5;
    const int wm   = wid >> 2;          // 0..3 -> M offset wm*32
    const int wn   = wid & 3;           // 0..3 -> N offset wn*32
    const int row0 = blockIdx.x * 128;

    const int m = tid >> 2;             // producer row 0..127
    const int h = tid & 3;              // k-quarter (16 floats) within chunk
    const int rr = min(row0 + m, N - 1);

    uint64_t xg, wg;
    asm("cvta.to.global.u64 %0, %1;" : "=l"(xg) : "l"((const void*)x));
    asm("cvta.to.global.u64 %0, %1;" : "=l"(wg) : "l"((const void*)g_wh));

    float acc[2][4][4];
    #pragma unroll
    for (int t = 0; t < 2; t++)
        #pragma unroll
        for (int nt = 0; nt < 4; nt++)
            #pragma unroll
            for (int j = 0; j < 4; j++) acc[t][nt][j] = 0.f;

    const uint32_t a_adr0 = sm + SM_AH + (wm * 32 + 0  + (lane & 15)) * 144 + ((lane >> 4) << 4);
    const uint32_t a_adr1 = sm + SM_AH + (wm * 32 + 16 + (lane & 15)) * 144 + ((lane >> 4) << 4);
    const uint32_t b_row  = (uint32_t)(wn * 32 + ((lane >> 4) << 3) + (lane & 7));
    const uint32_t b_koff = (uint32_t)(((lane >> 3) & 1) << 4);

    // B-copy indices (2 x 16B per thread)
    const int bn0 = tid >> 2;                 // idx = tid     -> n, kq
    const int bk0 = (tid & 3) * 2;
    // staging destinations (4 x 16B per thread)
    const uint32_t st_dst = sm + SM_ST + (uint32_t)((h * ST_HSTRIDE + m * 16) * 4);
    const uint64_t x_src  = xg + ((uint64_t)rr * 64 + h * 4) * 16;

    // ---- prologue: stage chunk 0 (A raw fp32) + B0 ----
    {
        #pragma unroll
        for (int p = 0; p < 4; p++)
            CP_ASYNC16(st_dst + p * 16, x_src + p * 16);
        #pragma unroll
        for (int q = 0; q < 2; q++) {
            uint32_t dst = sm + SM_B0 + (uint32_t)(bn0 * 144 + (bk0 + q) * 16);
            CP_ASYNC16(dst, wg + ((uint64_t)bn0 * 32 + 0 * 8 + bk0 + q) * 16);
        }
        CP_COMMIT();
    }

    for (int c = 0; c < 4; c++) {
        CP_WAIT0();
        __syncthreads();                // staging[c] + B[c&1] visible; A image free
        // ---- convert staged fp32 -> fp16 A image ----
        #pragma unroll
        for (int p = 0; p < 2; p++) {
            float4 f0 = *(const float4*)(smc + (st_dst - sm) + (p * 8 + 0) * 4);
            float4 f1 = *(const float4*)(smc + (st_dst - sm) + (p * 8 + 4) * 4);
            __half2 h0 = __floats2half2_rn(f0.x, f0.y);
            __half2 h1 = __floats2half2_rn(f0.z, f0.w);
            __half2 h2 = __floats2half2_rn(f1.x, f1.y);
            __half2 h3 = __floats2half2_rn(f1.z, f1.w);
            uint32_t off = (uint32_t)(m * 144 + h * 32 + p * 16);
            *(uint4*)(smc + SM_AH + off) = make_uint4(
                *(uint32_t*)&h0, *(uint32_t*)&h1, *(uint32_t*)&h2, *(uint32_t*)&h3);
        }
        __syncthreads();                // A image ready; staging consumed
        // ---- stage next chunk (overlaps compute below) ----
        if (c < 3) {
            #pragma unroll
            for (int p = 0; p < 4; p++)
                CP_ASYNC16(st_dst + p * 16, x_src + ((uint64_t)(c + 1) * 16) * 16 + p * 16);
            uint32_t bnext = (c & 1) ? SM_B0 : SM_B1;
            #pragma unroll
            for (int q = 0; q < 2; q++) {
                uint32_t dst = sm + bnext + (uint32_t)(bn0 * 144 + (bk0 + q) * 16);
                CP_ASYNC16(dst, wg + ((uint64_t)bn0 * 32 + (c + 1) * 8 + bk0 + q) * 16);
            }
            CP_COMMIT();
        }
        // ---- compute: 4 k16 steps, single MMA term ----
        const uint32_t b_adr = sm + ((c & 1) ? SM_B1 : SM_B0) + b_row * 144 + b_koff;
        #pragma unroll
        for (int ks = 0; ks < 4; ks++) {
            uint32_t ah0[4], ah1[4];
            LDSM_X4(ah0[0], ah0[1], ah0[2], ah0[3], a_adr0 + ks * 32);
            LDSM_X4(ah1[0], ah1[1], ah1[2], ah1[3], a_adr1 + ks * 32);
            #pragma unroll
            for (int j = 0; j < 2; j++) {      // 2 n16-groups
                uint32_t bh[4];
                LDSM_X4(bh[0], bh[1], bh[2], bh[3], b_adr + j * 16 * 144 + ks * 32);
                MMA_F16(acc[0][2 * j],     ah0, bh);
                MMA_F16(acc[1][2 * j],     ah1, bh);
                MMA_F16(acc[0][2 * j + 1], ah0, bh + 2);
                MMA_F16(acc[1][2 * j + 1], ah1, bh + 2);
            }
        }
    }

    // ---- epilogue: scale by dinv[row], write fp16 xwh ----
    uint32_t* xw = (uint32_t*)g_xwh;            // row stride 64 uint (half2)
    const int nb2 = wn * 16;                    // half2-base
    #pragma unroll
    for (int t = 0; t < 2; t++) {
        int r_lo = row0 + wm * 32 + t * 16 + (lane >> 2);
        int r_hi = r_lo + 8;
        float d_lo = (r_lo < N) ? g_dinv[r_lo] : 0.f;
        float d_hi = (r_hi < N) ? g_dinv[r_hi] : 0.f;
        #pragma unroll
        for (int nt = 0; nt < 4; nt++) {
            int ci = nb2 + nt * 4 + (lane & 3);
            if (r_lo < N) {
                __half2 p = __floats2half2_rn(acc[t][nt][0] * d_lo, acc[t][nt][1] * d_lo);
                xw[(size_t)r_lo * 64 + ci] = *(uint32_t*)&p;
            }
            if (r_hi < N) {
                __half2 p = __floats2half2_rn(acc[t][nt][2] * d_hi, acc[t][nt][3] * d_hi);
                xw[(size_t)r_hi * 64 + ci] = *(uint32_t*)&p;
            }
        }
    }
}

// ---------------------------------------------------------------------------
__device__ __forceinline__ void add_h4(float4& a, uint2 u) {
    float2 f0 = __half22float2(*(__half2*)&u.x);
    float2 f1 = __half22float2(*(__half2*)&u.y);
    a.x += f0.x; a.y += f0.y; a.z += f1.x; a.w += f1.y;
}

// 6) aggregation: one warp per node, fp16 gathers, fp32 accumulation.
__global__ void __launch_bounds__(256) agg_kernel(const float* __restrict__ b,
                                                  float* __restrict__ out, int N) {
    int warp = (blockIdx.x * blockDim.x + threadIdx.x) >> 5;
    int lane = threadIdx.x & 31;
    if (warp >= N) return;
    int node = warp;

    const uint2* xw = (const uint2*)g_xwh;      // row stride 32 uint2
    float4 acc = make_float4(0.f, 0.f, 0.f, 0.f);
    add_h4(acc, xw[(size_t)node * 32 + lane]);  // self-loop
    float4 bb = ((const float4*)b)[lane];

    int e   = g_rowptr[node];
    int end = g_rowptr[node + 1];
    for (; e + 8 <= end; e += 8) {
        uint2 u[8];
        #pragma unroll
        for (int q = 0; q < 8; q++)
            u[q] = xw[(size_t)g_srcid[e + q] * 32 + lane];
        #pragma unroll
        for (int q = 0; q < 8; q++) add_h4(acc, u[q]);
    }
    if (e + 4 <= end) {
        uint2 u[4];
        #pragma unroll
        for (int q = 0; q < 4; q++)
            u[q] = xw[(size_t)g_srcid[e + q] * 32 + lane];
        #pragma unroll
        for (int q = 0; q < 4; q++) add_h4(acc, u[q]);
        e += 4;
    }
    for (; e < end; e++)
        add_h4(acc, xw[(size_t)g_srcid[e] * 32 + lane]);

    float di = g_dinv[node];
    float4 o;
    o.x = fmaxf(fmaf(di, acc.x, bb.x), 0.f);
    o.y = fmaxf(fmaf(di, acc.y, bb.y), 0.f);
    o.z = fmaxf(fmaf(di, acc.z, bb.z), 0.f);
    o.w = fmaxf(fmaf(di, acc.w, bb.w), 0.f);
    ((float4*)out)[(size_t)node * 32 + lane] = o;
}

// ---------------------------------------------------------------------------
extern "C" void kernel_launch(void* const* d_in, const int* in_sizes, int n_in,
                              void* d_out, int out_size) {
    const float* x  = (const float*)d_in[0];
    const void*  ei = d_in[1];                 // [2, E] int32 or int64 (probed)
    const float* W  = (const float*)d_in[2];
    const float* b  = (const float*)d_in[3];
    float*       out = (float*)d_out;

    const int N = in_sizes[0] / 256;   // 40000
    const int E = in_sizes[1] / 2;     // 640000

    cudaFuncSetAttribute(gemm_kernel, cudaFuncAttributeMaxDynamicSharedMemorySize, SM_TOT);

    // Order chosen so the ncu sample slot (4th launch) captures the GEMM.
    init_kernel<<<(N + 255) / 256, 256>>>((const int*)ei, W, N);
    count_kernel<<<(E + 255) / 256, 256>>>(ei, E, N);
    scan_kernel<<<1, 1024>>>(N);
    gemm_kernel<<<(N + 127) / 128, 512, SM_TOT>>>(x, N);
    scatter_kernel<<<(E + 255) / 256, 256>>>(E, N);
    agg_kernel<<<(N * 32 + 255) / 256, 256>>>(b, out, N);
}

// round 11
// speedup vs baseline: 1.0641x; 1.0641x over previous
#include <cuda_runtime.h>
#include <cuda_bf16.h>
#include <cuda_fp16.h>
#include <cstdint>

// Problem shape: N=40000 nodes, F_in=256, F_out=128, E=640000 edges.
static constexpr int MAXN = 40000;
static constexpr int MAXE = 640000;

// Scratch (allocation-free rule: __device__ globals)
__device__ int    g_is64;               // 1 if edge_index is int64, 0 if int32
__device__ __align__(16) int g_cnt[MAXN];   // in-degree; reused as scatter cursor
__device__ int    g_rowptr[MAXN + 1];   // CSR row pointers (by dst)
__device__ float  g_dinv[MAXN];         // rsqrt(deg+1)
__device__ int    g_srcid[MAXE];        // CSR column (source node) ids
__device__ __align__(16) __half g_xwh[MAXN * 128];  // fp16 raw (x@W)[i] (UNSCALED)
// W^T image: [n=128][k=256] fp16
__device__ __align__(16) __half g_wh[128 * 256];

// ---------------------------------------------------------------------------
__device__ __forceinline__ uint32_t smem_u32(const void* p) {
    uint32_t a;
    asm("{ .reg .u64 t; cvta.to.shared.u64 t, %1; cvt.u32.u64 %0, t; }" : "=r"(a) : "l"(p));
    return a;
}
#define LDSM_X4(r0, r1, r2, r3, adr)                                              \
    asm volatile("ldmatrix.sync.aligned.m8n8.x4.shared.b16 {%0,%1,%2,%3}, [%4];"  \
                 : "=r"(r0), "=r"(r1), "=r"(r2), "=r"(r3) : "r"(adr))
#define MMA_F16(c, a, b)                                                          \
    asm volatile("mma.sync.aligned.m16n8k16.row.col.f32.f16.f16.f32 "             \
                 "{%0,%1,%2,%3}, {%4,%5,%6,%7}, {%8,%9}, {%0,%1,%2,%3};"          \
                 : "+f"((c)[0]), "+f"((c)[1]), "+f"((c)[2]), "+f"((c)[3])         \
                 : "r"((a)[0]), "r"((a)[1]), "r"((a)[2]), "r"((a)[3]),            \
                   "r"((b)[0]), "r"((b)[1]))

// ---------------------------------------------------------------------------
// 1) init: zero counters; block 0 probes index dtype; first 32768 threads
//    build the W^T fp16 image.
__global__ void init_kernel(const int* __restrict__ ei32,
                            const float* __restrict__ W, int N) {
    int i = blockIdx.x * blockDim.x + threadIdx.x;
    if (i < N) g_cnt[i] = 0;
    if (i < 128 * 256) {
        int k = i & 255;
        int n = i >> 8;
        g_wh[n * 256 + k] = __float2half_rn(W[(size_t)k * 128 + n]);
    }
    if (blockIdx.x == 0) {
        __shared__ int red[8];
        int tid = threadIdx.x;
        int acc = 0;
        for (int k = tid; k < 1024; k += 256)
            acc |= ei32[2 * k + 1];              // int64 high halves
        #pragma unroll
        for (int off = 16; off > 0; off >>= 1)
            acc |= __shfl_down_sync(0xFFFFFFFFu, acc, off);
        if ((tid & 31) == 0) red[tid >> 5] = acc;
        __syncthreads();
        if (tid == 0) {
            int r = 0;
            #pragma unroll
            for (int w = 0; w < 8; w++) r |= red[w];
            g_is64 = (r == 0) ? 1 : 0;
        }
    }
}

__device__ __forceinline__ int load_idx(const void* ei, long long i, int is64) {
    if (is64) return (int)((const long long*)ei)[i];
    return ((const int*)ei)[i];
}

// 2) histogram of dst
__global__ void count_kernel(const void* __restrict__ ei, int E, int N) {
    int e = blockIdx.x * blockDim.x + threadIdx.x;
    if (e < E) {
        int is64 = g_is64;
        unsigned d = (unsigned)load_idx(ei, (long long)E + e, is64);
        if (d < (unsigned)N) atomicAdd(&g_cnt[d], 1);
    }
}

// 3) exclusive scan of g_cnt -> g_rowptr; fused dinv. 4 elements/thread.
__global__ void __launch_bounds__(1024) scan_kernel(int N) {
    __shared__ int shw[32];
    __shared__ int carry;
    int tid = threadIdx.x, lane = tid & 31, warp = tid >> 5;
    if (tid == 0) { carry = 0; g_rowptr[0] = 0; }
    __syncthreads();
    for (int base = 0; base < N; base += 4096) {
        int i0 = base + tid * 4;
        int v[4];
        if (i0 + 3 < N) {
            int4 q = *(const int4*)&g_cnt[i0];
            v[0] = q.x; v[1] = q.y; v[2] = q.z; v[3] = q.w;
        } else {
            #pragma unroll
            for (int j = 0; j < 4; j++) v[j] = (i0 + j < N) ? g_cnt[i0 + j] : 0;
        }
        int tsum = v[0] + v[1] + v[2] + v[3];
        int s = tsum;
        #pragma unroll
        for (int off = 1; off < 32; off <<= 1) {
            int t = __shfl_up_sync(0xFFFFFFFFu, s, off);
            if (lane >= off) s += t;
        }
        if (lane == 31) shw[warp] = s;
        __syncthreads();
        if (warp == 0) {
            int ws = shw[lane];
            #pragma unroll
            for (int off = 1; off < 32; off <<= 1) {
                int t = __shfl_up_sync(0xFFFFFFFFu, ws, off);
                if (lane >= off) ws += t;
            }
            shw[lane] = ws;
        }
        __syncthreads();
        int run = (s - tsum) + (warp > 0 ? shw[warp - 1] : 0) + carry;
        #pragma unroll
        for (int j = 0; j < 4; j++) {
            run += v[j];
            if (i0 + j < N) {
                g_rowptr[i0 + j + 1] = run;
                g_dinv[i0 + j] = rsqrtf((float)v[j] + 1.0f);
            }
        }
        __syncthreads();
        if (tid == 0) carry += shw[31];
        __syncthreads();
    }
}

// 4) scatter edge source ids into CSR slots (g_cnt doubles as down-cursor;
//    ends with g_cnt back at all-zero)
__global__ void scatter_kernel(const void* __restrict__ ei, int E, int N) {
    int e = blockIdx.x * blockDim.x + threadIdx.x;
    if (e < E) {
        int is64 = g_is64;
        unsigned d = (unsigned)load_idx(ei, (long long)E + e, is64);
        unsigned s = (unsigned)load_idx(ei, e, is64);
        if (d < (unsigned)N && s < (unsigned)N) {
            int v = atomicSub(&g_cnt[d], 1);          // old value in [1..deg]
            g_srcid[g_rowptr[d] + v - 1] = (int)s;
        }
    }
}

// ---------------------------------------------------------------------------
// 5) GEMM via mma.sync fp16 (R9 structure, no dinv in epilogue):
//    xwh[i,:] = fp16( x[i,:] @ W )
//    CTA 128Mx128N, 16 warps (4Mx4N), warp 32Mx32N; K chunks of 64.
static constexpr int SM_AH  = 0;
static constexpr int SM_BH  = 18432;
static constexpr int SM_TOT = 36864;

__global__ void __launch_bounds__(512, 2)
gemm_kernel(const float* __restrict__ x, int N) {
    extern __shared__ unsigned char smc[];
    const uint32_t sm = smem_u32(smc);
    const int tid  = threadIdx.x;
    const int lane = tid & 31;
    const int wid  = tid >> 5;
    const int wm   = wid >> 2;          // 0..3 -> M offset wm*32
    const int wn   = wid & 3;           // 0..3 -> N offset wn*32
    const int row0 = blockIdx.x * 128;

    const float4* X4 = (const float4*)x;          // row stride 64 float4
    const uint4*  WH = (const uint4*)g_wh;        // row = 32 uint4

    float acc[2][4][4];
    #pragma unroll
    for (int t = 0; t < 2; t++)
        #pragma unroll
        for (int nt = 0; nt < 4; nt++)
            #pragma unroll
            for (int j = 0; j < 4; j++) acc[t][nt][j] = 0.f;

    const int m = tid >> 2;             // producer row 0..127
    const int h = tid & 3;              // k-quarter (16 floats) within chunk
    const int rr = min(row0 + m, N - 1);

    const uint32_t a_adr0 = sm + SM_AH + (wm * 32 + 0  + (lane & 15)) * 144 + ((lane >> 4) << 4);
    const uint32_t a_adr1 = sm + SM_AH + (wm * 32 + 16 + (lane & 15)) * 144 + ((lane >> 4) << 4);
    const uint32_t b_row  = (uint32_t)(wn * 32 + ((lane >> 4) << 3) + (lane & 7));
    const uint32_t b_koff = (uint32_t)(((lane >> 3) & 1) << 4);
    const uint32_t b_adr  = sm + SM_BH + b_row * 144 + b_koff;

    for (int c = 0; c < 4; c++) {
        if (c > 0) __syncthreads();     // previous compute done before overwrite
        // ---- A: load 4 float4 -> fp16 -> STS (2x uint4) ----
        #pragma unroll
        for (int p = 0; p < 2; p++) {
            float4 f0 = X4[(size_t)rr * 64 + c * 16 + h * 4 + p * 2];
            float4 f1 = X4[(size_t)rr * 64 + c * 16 + h * 4 + p * 2 + 1];
            __half2 h0 = __floats2half2_rn(f0.x, f0.y);
            __half2 h1 = __floats2half2_rn(f0.z, f0.w);
            __half2 h2 = __floats2half2_rn(f1.x, f1.y);
            __half2 h3 = __floats2half2_rn(f1.z, f1.w);
            uint32_t off = (uint32_t)(m * 144 + h * 32 + p * 16);
            *(uint4*)(smc + SM_AH + off) = make_uint4(
                *(uint32_t*)&h0, *(uint32_t*)&h1, *(uint32_t*)&h2, *(uint32_t*)&h3);
        }
        // ---- B chunk copy, 2 uint4 per thread (L2-resident) ----
        {
            int n   = tid >> 2;
            int kq  = (tid & 3) * 2;
            uint32_t dst = (uint32_t)(n * 144 + kq * 16);
            uint4 v0 = WH[n * 32 + c * 8 + kq];
            uint4 v1 = WH[n * 32 + c * 8 + kq + 1];
            *(uint4*)(smc + SM_BH + dst)      = v0;
            *(uint4*)(smc + SM_BH + dst + 16) = v1;
        }
        __syncthreads();

        // ---- compute: 4 k16 steps, single MMA term ----
        #pragma unroll
        for (int ks = 0; ks < 4; ks++) {
            uint32_t ah0[4], ah1[4];
            LDSM_X4(ah0[0], ah0[1], ah0[2], ah0[3], a_adr0 + ks * 32);
            LDSM_X4(ah1[0], ah1[1], ah1[2], ah1[3], a_adr1 + ks * 32);
            #pragma unroll
            for (int j = 0; j < 2; j++) {      // 2 n16-groups
                uint32_t bh[4];
                LDSM_X4(bh[0], bh[1], bh[2], bh[3], b_adr + j * 16 * 144 + ks * 32);
                MMA_F16(acc[0][2 * j],     ah0, bh);
                MMA_F16(acc[1][2 * j],     ah1, bh);
                MMA_F16(acc[0][2 * j + 1], ah0, bh + 2);
                MMA_F16(acc[1][2 * j + 1], ah1, bh + 2);
            }
        }
    }

    // ---- epilogue: write raw fp16 xwh (dinv applied in agg) ----
    uint32_t* xw = (uint32_t*)g_xwh;            // row stride 64 uint (half2)
    const int nb2 = wn * 16;                    // half2-base
    #pragma unroll
    for (int t = 0; t < 2; t++) {
        int r_lo = row0 + wm * 32 + t * 16 + (lane >> 2);
        int r_hi = r_lo + 8;
        #pragma unroll
        for (int nt = 0; nt < 4; nt++) {
            int ci = nb2 + nt * 4 + (lane & 3);
            if (r_lo < N) {
                __half2 p = __floats2half2_rn(acc[t][nt][0], acc[t][nt][1]);
                xw[(size_t)r_lo * 64 + ci] = *(uint32_t*)&p;
            }
            if (r_hi < N) {
                __half2 p = __floats2half2_rn(acc[t][nt][2], acc[t][nt][3]);
                xw[(size_t)r_hi * 64 + ci] = *(uint32_t*)&p;
            }
        }
    }
}

// ---------------------------------------------------------------------------
__device__ __forceinline__ void fma_h4(float4& a, uint2 u, float s) {
    float2 f0 = __half22float2(*(__half2*)&u.x);
    float2 f1 = __half22float2(*(__half2*)&u.y);
    a.x = fmaf(s, f0.x, a.x); a.y = fmaf(s, f0.y, a.y);
    a.z = fmaf(s, f1.x, a.z); a.w = fmaf(s, f1.y, a.w);
}

// 6) aggregation: one warp per node; per-source dinv folded in here.
//    out[i] = relu( dinv_i * ( dinv_i*xw_i + sum_e dinv_s*xw_s ) + b )
__global__ void __launch_bounds__(256) agg_kernel(const float* __restrict__ b,
                                                  float* __restrict__ out, int N) {
    int warp = (blockIdx.x * blockDim.x + threadIdx.x) >> 5;
    int lane = threadIdx.x & 31;
    if (warp >= N) return;
    int node = warp;

    const uint2* xw = (const uint2*)g_xwh;      // row stride 32 uint2
    float di = g_dinv[node];
    float4 acc = make_float4(0.f, 0.f, 0.f, 0.f);
    fma_h4(acc, xw[(size_t)node * 32 + lane], di);   // self-loop (di, scaled di again at end)
    float4 bb = ((const float4*)b)[lane];

    int e   = g_rowptr[node];
    int end = g_rowptr[node + 1];
    for (; e + 8 <= end; e += 8) {
        int s[8]; float ds[8]; uint2 u[8];
        #pragma unroll
        for (int q = 0; q < 8; q++) s[q] = g_srcid[e + q];
        #pragma unroll
        for (int q = 0; q < 8; q++) {
            ds[q] = g_dinv[s[q]];
            u[q]  = xw[(size_t)s[q] * 32 + lane];
        }
        #pragma unroll
        for (int q = 0; q < 8; q++) fma_h4(acc, u[q], ds[q]);
    }
    if (e + 4 <= end) {
        int s[4]; float ds[4]; uint2 u[4];
        #pragma unroll
        for (int q = 0; q < 4; q++) s[q] = g_srcid[e + q];
        #pragma unroll
        for (int q = 0; q < 4; q++) {
            ds[q] = g_dinv[s[q]];
            u[q]  = xw[(size_t)s[q] * 32 + lane];
        }
        #pragma unroll
        for (int q = 0; q < 4; q++) fma_h4(acc, u[q], ds[q]);
        e += 4;
    }
    for (; e < end; e++) {
        int s = g_srcid[e];
        fma_h4(acc, xw[(size_t)s * 32 + lane], g_dinv[s]);
    }

    float4 o;
    o.x = fmaxf(fmaf(di, acc.x, bb.x), 0.f);
    o.y = fmaxf(fmaf(di, acc.y, bb.y), 0.f);
    o.z = fmaxf(fmaf(di, acc.z, bb.z), 0.f);
    o.w = fmaxf(fmaf(di, acc.w, bb.w), 0.f);
    ((float4*)out)[(size_t)node * 32 + lane] = o;
}

// ---------------------------------------------------------------------------
extern "C" void kernel_launch(void* const* d_in, const int* in_sizes, int n_in,
                              void* d_out, int out_size) {
    const float* x  = (const float*)d_in[0];
    const void*  ei = d_in[1];                 // [2, E] int32 or int64 (probed)
    const float* W  = (const float*)d_in[2];
    const float* b  = (const float*)d_in[3];
    float*       out = (float*)d_out;

    const int N = in_sizes[0] / 256;   // 40000
    const int E = in_sizes[1] / 2;     // 640000

    // One-time host resources (created on the pre-capture correctness call;
    // record/wait below become graph dependencies during capture).
    static cudaStream_t s_gemm = nullptr;
    static cudaEvent_t  ev_init = nullptr, ev_gemm = nullptr;
    if (s_gemm == nullptr) {
        cudaStreamCreateWithFlags(&s_gemm, cudaStreamNonBlocking);
        cudaEventCreateWithFlags(&ev_init, cudaEventDisableTiming);
        cudaEventCreateWithFlags(&ev_gemm, cudaEventDisableTiming);
        cudaFuncSetAttribute(gemm_kernel,
                             cudaFuncAttributeMaxDynamicSharedMemorySize, SM_TOT);
    }

    // init -> fork: [gemm] on s_gemm  ||  [count -> scan -> scatter] on default
    // join -> agg
    init_kernel<<<(N + 255) / 256, 256>>>((const int*)ei, W, N);
    cudaEventRecord(ev_init, 0);
    cudaStreamWaitEvent(s_gemm, ev_init, 0);
    gemm_kernel<<<(N + 127) / 128, 512, SM_TOT, s_gemm>>>(x, N);
    cudaEventRecord(ev_gemm, s_gemm);

    count_kernel<<<(E + 255) / 256, 256>>>(ei, E, N);
    scan_kernel<<<1, 1024>>>(N);
    scatter_kernel<<<(E + 255) / 256, 256>>>(ei, E, N);

    cudaStreamWaitEvent(0, ev_gemm, 0);
    agg_kernel<<<(N * 32 + 255) / 256, 256>>>(b, out, N);
}

// round 12
// speedup vs baseline: 1.5110x; 1.4200x over previous
#include <cuda_runtime.h>
#include <cuda_bf16.h>
#include <cuda_fp16.h>
#include <cstdint>

// Problem shape: N=40000 nodes, F_in=256, F_out=128, E=640000 edges.
static constexpr int MAXN = 40000;
static constexpr int MAXE = 640000;

// Scratch (allocation-free rule: __device__ globals)
__device__ int    g_is64;               // 1 if edge_index is int64, 0 if int32
__device__ __align__(16) int g_cnt[MAXN];   // in-degree; reused as scatter cursor
__device__ int    g_rowptr[MAXN + 1];   // CSR row pointers (by dst)
__device__ float  g_dinv[MAXN];         // rsqrt(deg+1)
__device__ int    g_srcid[MAXE];        // CSR column (source node) ids
__device__ unsigned long long g_state[64];  // decoupled-lookback scan state
__device__ __align__(16) __half g_xwh[MAXN * 128];  // fp16 raw (x@W)[i] (UNSCALED)
// W^T image: [n=128][k=256] fp16
__device__ __align__(16) __half g_wh[128 * 256];

// ---------------------------------------------------------------------------
__device__ __forceinline__ uint32_t smem_u32(const void* p) {
    uint32_t a;
    asm("{ .reg .u64 t; cvta.to.shared.u64 t, %1; cvt.u32.u64 %0, t; }" : "=r"(a) : "l"(p));
    return a;
}
#define LDSM_X4(r0, r1, r2, r3, adr)                                              \
    asm volatile("ldmatrix.sync.aligned.m8n8.x4.shared.b16 {%0,%1,%2,%3}, [%4];"  \
                 : "=r"(r0), "=r"(r1), "=r"(r2), "=r"(r3) : "r"(adr))
#define MMA_F16(c, a, b)                                                          \
    asm volatile("mma.sync.aligned.m16n8k16.row.col.f32.f16.f16.f32 "             \
                 "{%0,%1,%2,%3}, {%4,%5,%6,%7}, {%8,%9}, {%0,%1,%2,%3};"          \
                 : "+f"((c)[0]), "+f"((c)[1]), "+f"((c)[2]), "+f"((c)[3])         \
                 : "r"((a)[0]), "r"((a)[1]), "r"((a)[2]), "r"((a)[3]),            \
                   "r"((b)[0]), "r"((b)[1]))

// ---------------------------------------------------------------------------
// 1) init: zero counters + scan state; block 0 probes index dtype; first
//    32768 threads build the W^T fp16 image.
__global__ void init_kernel(const int* __restrict__ ei32,
                            const float* __restrict__ W, int N) {
    int i = blockIdx.x * blockDim.x + threadIdx.x;
    if (i < N) g_cnt[i] = 0;
    if (i < 64) g_state[i] = 0ULL;
    if (i < 128 * 256) {
        int k = i & 255;
        int n = i >> 8;
        g_wh[n * 256 + k] = __float2half_rn(W[(size_t)k * 128 + n]);
    }
    if (blockIdx.x == 0) {
        __shared__ int red[8];
        int tid = threadIdx.x;
        int acc = 0;
        for (int k = tid; k < 1024; k += 256)
            acc |= ei32[2 * k + 1];              // int64 high halves
        #pragma unroll
        for (int off = 16; off > 0; off >>= 1)
            acc |= __shfl_down_sync(0xFFFFFFFFu, acc, off);
        if ((tid & 31) == 0) red[tid >> 5] = acc;
        __syncthreads();
        if (tid == 0) {
            int r = 0;
            #pragma unroll
            for (int w = 0; w < 8; w++) r |= red[w];
            g_is64 = (r == 0) ? 1 : 0;
        }
    }
}

__device__ __forceinline__ int load_idx(const void* ei, long long i, int is64) {
    if (is64) return (int)((const long long*)ei)[i];
    return ((const int*)ei)[i];
}

// 2) histogram of dst
__global__ void count_kernel(const void* __restrict__ ei, int E, int N) {
    int e = blockIdx.x * blockDim.x + threadIdx.x;
    if (e < E) {
        int is64 = g_is64;
        unsigned d = (unsigned)load_idx(ei, (long long)E + e, is64);
        if (d < (unsigned)N) atomicAdd(&g_cnt[d], 1);
    }
}

// 3) multi-block exclusive scan (decoupled lookback); fused dinv.
//    1024 threads/block, 1 element/thread, grid = ceil(N/1024) (<= 64 blocks).
__global__ void __launch_bounds__(1024) scan_kernel(int N) {
    __shared__ int shw[32];
    __shared__ long long sh_excl;
    const int tid  = threadIdx.x;
    const int lane = tid & 31;
    const int warp = tid >> 5;
    const int b    = blockIdx.x;
    const int i    = b * 1024 + tid;

    int v = (i < N) ? g_cnt[i] : 0;
    if (i < N) g_dinv[i] = rsqrtf((float)v + 1.0f);

    // block-local inclusive scan
    int s = v;
    #pragma unroll
    for (int off = 1; off < 32; off <<= 1) {
        int t = __shfl_up_sync(0xFFFFFFFFu, s, off);
        if (lane >= off) s += t;
    }
    if (lane == 31) shw[warp] = s;
    __syncthreads();
    if (warp == 0) {
        int ws = shw[lane];
        #pragma unroll
        for (int off = 1; off < 32; off <<= 1) {
            int t = __shfl_up_sync(0xFFFFFFFFu, ws, off);
            if (lane >= off) ws += t;
        }
        shw[lane] = ws;
    }
    __syncthreads();
    const int incl  = s + (warp > 0 ? shw[warp - 1] : 0);
    const int total = shw[31];

    // decoupled lookback (thread 0)
    if (tid == 0) {
        if (b == 0) {
            atomicExch(&g_state[0], (2ULL << 32) | (unsigned long long)(unsigned)total);
            sh_excl = 0;
        } else {
            // publish aggregate so later blocks can progress
            atomicExch(&g_state[b], (1ULL << 32) | (unsigned long long)(unsigned)total);
            long long excl = 0;
            for (int p = b - 1; p >= 0; ) {
                unsigned long long st;
                do { st = atomicAdd(&g_state[p], 0ULL); } while ((st >> 32) == 0ULL);
                excl += (long long)(st & 0xFFFFFFFFULL);
                if ((st >> 32) == 2ULL) break;
                p--;
            }
            atomicExch(&g_state[b],
                       (2ULL << 32) | (unsigned long long)(unsigned)(excl + total));
            sh_excl = excl;
        }
    }
    __syncthreads();
    const long long excl = sh_excl;

    if (i < N) g_rowptr[i + 1] = (int)(excl + incl);
    if (i == 0) g_rowptr[0] = 0;
}

// 4) scatter edge source ids into CSR slots (g_cnt doubles as down-cursor)
__global__ void scatter_kernel(const void* __restrict__ ei, int E, int N) {
    int e = blockIdx.x * blockDim.x + threadIdx.x;
    if (e < E) {
        int is64 = g_is64;
        unsigned d = (unsigned)load_idx(ei, (long long)E + e, is64);
        unsigned s = (unsigned)load_idx(ei, e, is64);
        if (d < (unsigned)N && s < (unsigned)N) {
            int v = atomicSub(&g_cnt[d], 1);          // old value in [1..deg]
            g_srcid[g_rowptr[d] + v - 1] = (int)s;
        }
    }
}

// ---------------------------------------------------------------------------
// 5) GEMM via mma.sync fp16: xwh[i,:] = fp16( x[i,:] @ W )   (raw, no dinv)
//    CTA 128Mx128N, 16 warps (4Mx4N), warp 32Mx32N; K chunks of 64.
static constexpr int SM_AH  = 0;
static constexpr int SM_BH  = 18432;
static constexpr int SM_TOT = 36864;

__global__ void __launch_bounds__(512, 2)
gemm_kernel(const float* __restrict__ x, int N) {
    extern __shared__ unsigned char smc[];
    const uint32_t sm = smem_u32(smc);
    const int tid  = threadIdx.x;
    const int lane = tid & 31;
    const int wid  = tid >> 5;
    const int wm   = wid >> 2;          // 0..3 -> M offset wm*32
    const int wn   = wid & 3;           // 0..3 -> N offset wn*32
    const int row0 = blockIdx.x * 128;

    const float4* X4 = (const float4*)x;          // row stride 64 float4
    const uint4*  WH = (const uint4*)g_wh;        // row = 32 uint4

    float acc[2][4][4];
    #pragma unroll
    for (int t = 0; t < 2; t++)
        #pragma unroll
        for (int nt = 0; nt < 4; nt++)
            #pragma unroll
            for (int j = 0; j < 4; j++) acc[t][nt][j] = 0.f;

    const int m = tid >> 2;             // producer row 0..127
    const int h = tid & 3;              // k-quarter (16 floats) within chunk
    const int rr = min(row0 + m, N - 1);

    const uint32_t a_adr0 = sm + SM_AH + (wm * 32 + 0  + (lane & 15)) * 144 + ((lane >> 4) << 4);
    const uint32_t a_adr1 = sm + SM_AH + (wm * 32 + 16 + (lane & 15)) * 144 + ((lane >> 4) << 4);
    const uint32_t b_row  = (uint32_t)(wn * 32 + ((lane >> 4) << 3) + (lane & 7));
    const uint32_t b_koff = (uint32_t)(((lane >> 3) & 1) << 4);
    const uint32_t b_adr  = sm + SM_BH + b_row * 144 + b_koff;

    for (int c = 0; c < 4; c++) {
        if (c > 0) __syncthreads();     // previous compute done before overwrite
        // ---- A: load 4 float4 -> fp16 -> STS (2x uint4) ----
        #pragma unroll
        for (int p = 0; p < 2; p++) {
            float4 f0 = X4[(size_t)rr * 64 + c * 16 + h * 4 + p * 2];
            float4 f1 = X4[(size_t)rr * 64 + c * 16 + h * 4 + p * 2 + 1];
            __half2 h0 = __floats2half2_rn(f0.x, f0.y);
            __half2 h1 = __floats2half2_rn(f0.z, f0.w);
            __half2 h2 = __floats2half2_rn(f1.x, f1.y);
            __half2 h3 = __floats2half2_rn(f1.z, f1.w);
            uint32_t off = (uint32_t)(m * 144 + h * 32 + p * 16);
            *(uint4*)(smc + SM_AH + off) = make_uint4(
                *(uint32_t*)&h0, *(uint32_t*)&h1, *(uint32_t*)&h2, *(uint32_t*)&h3);
        }
        // ---- B chunk copy, 2 uint4 per thread (L2-resident) ----
        {
            int n   = tid >> 2;
            int kq  = (tid & 3) * 2;
            uint32_t dst = (uint32_t)(n * 144 + kq * 16);
            uint4 v0 = WH[n * 32 + c * 8 + kq];
            uint4 v1 = WH[n * 32 + c * 8 + kq + 1];
            *(uint4*)(smc + SM_BH + dst)      = v0;
            *(uint4*)(smc + SM_BH + dst + 16) = v1;
        }
        __syncthreads();

        // ---- compute: 4 k16 steps, single MMA term ----
        #pragma unroll
        for (int ks = 0; ks < 4; ks++) {
            uint32_t ah0[4], ah1[4];
            LDSM_X4(ah0[0], ah0[1], ah0[2], ah0[3], a_adr0 + ks * 32);
            LDSM_X4(ah1[0], ah1[1], ah1[2], ah1[3], a_adr1 + ks * 32);
            #pragma unroll
            for (int j = 0; j < 2; j++) {      // 2 n16-groups
                uint32_t bh[4];
                LDSM_X4(bh[0], bh[1], bh[2], bh[3], b_adr + j * 16 * 144 + ks * 32);
                MMA_F16(acc[0][2 * j],     ah0, bh);
                MMA_F16(acc[1][2 * j],     ah1, bh);
                MMA_F16(acc[0][2 * j + 1], ah0, bh + 2);
                MMA_F16(acc[1][2 * j + 1], ah1, bh + 2);
            }
        }
    }

    // ---- epilogue: write raw fp16 xwh (dinv applied in agg) ----
    uint32_t* xw = (uint32_t*)g_xwh;            // row stride 64 uint (half2)
    const int nb2 = wn * 16;                    // half2-base
    #pragma unroll
    for (int t = 0; t < 2; t++) {
        int r_lo = row0 + wm * 32 + t * 16 + (lane >> 2);
        int r_hi = r_lo + 8;
        #pragma unroll
        for (int nt = 0; nt < 4; nt++) {
            int ci = nb2 + nt * 4 + (lane & 3);
            if (r_lo < N) {
                __half2 p = __floats2half2_rn(acc[t][nt][0], acc[t][nt][1]);
                xw[(size_t)r_lo * 64 + ci] = *(uint32_t*)&p;
            }
            if (r_hi < N) {
                __half2 p = __floats2half2_rn(acc[t][nt][2], acc[t][nt][3]);
                xw[(size_t)r_hi * 64 + ci] = *(uint32_t*)&p;
            }
        }
    }
}

// ---------------------------------------------------------------------------
__device__ __forceinline__ void fma_h4(float4& a, uint2 u, float s) {
    float2 f0 = __half22float2(*(__half2*)&u.x);
    float2 f1 = __half22float2(*(__half2*)&u.y);
    a.x = fmaf(s, f0.x, a.x); a.y = fmaf(s, f0.y, a.y);
    a.z = fmaf(s, f1.x, a.z); a.w = fmaf(s, f1.y, a.w);
}

// 6) aggregation: one warp per node; per-source dinv folded in here.
//    out[i] = relu( dinv_i * ( dinv_i*xw_i + sum_e dinv_s*xw_s ) + b )
__global__ void __launch_bounds__(256) agg_kernel(const float* __restrict__ b,
                                                  float* __restrict__ out, int N) {
    int warp = (blockIdx.x * blockDim.x + threadIdx.x) >> 5;
    int lane = threadIdx.x & 31;
    if (warp >= N) return;
    int node = warp;

    const uint2* xw = (const uint2*)g_xwh;      // row stride 32 uint2
    float di = g_dinv[node];
    float4 acc = make_float4(0.f, 0.f, 0.f, 0.f);
    fma_h4(acc, xw[(size_t)node * 32 + lane], di);   // self-loop
    float4 bb = ((const float4*)b)[lane];

    int e   = g_rowptr[node];
    int end = g_rowptr[node + 1];
    for (; e + 8 <= end; e += 8) {
        int s[8]; float ds[8]; uint2 u[8];
        #pragma unroll
        for (int q = 0; q < 8; q++) s[q] = g_srcid[e + q];
        #pragma unroll
        for (int q = 0; q < 8; q++) {
            ds[q] = g_dinv[s[q]];
            u[q]  = xw[(size_t)s[q] * 32 + lane];
        }
        #pragma unroll
        for (int q = 0; q < 8; q++) fma_h4(acc, u[q], ds[q]);
    }
    if (e + 4 <= end) {
        int s[4]; float ds[4]; uint2 u[4];
        #pragma unroll
        for (int q = 0; q < 4; q++) s[q] = g_srcid[e + q];
        #pragma unroll
        for (int q = 0; q < 4; q++) {
            ds[q] = g_dinv[s[q]];
            u[q]  = xw[(size_t)s[q] * 32 + lane];
        }
        #pragma unroll
        for (int q = 0; q < 4; q++) fma_h4(acc, u[q], ds[q]);
        e += 4;
    }
    for (; e < end; e++) {
        int s = g_srcid[e];
        fma_h4(acc, xw[(size_t)s * 32 + lane], g_dinv[s]);
    }

    float4 o;
    o.x = fmaxf(fmaf(di, acc.x, bb.x), 0.f);
    o.y = fmaxf(fmaf(di, acc.y, bb.y), 0.f);
    o.z = fmaxf(fmaf(di, acc.z, bb.z), 0.f);
    o.w = fmaxf(fmaf(di, acc.w, bb.w), 0.f);
    ((float4*)out)[(size_t)node * 32 + lane] = o;
}

// ---------------------------------------------------------------------------
extern "C" void kernel_launch(void* const* d_in, const int* in_sizes, int n_in,
                              void* d_out, int out_size) {
    const float* x  = (const float*)d_in[0];
    const void*  ei = d_in[1];                 // [2, E] int32 or int64 (probed)
    const float* W  = (const float*)d_in[2];
    const float* b  = (const float*)d_in[3];
    float*       out = (float*)d_out;

    const int N = in_sizes[0] / 256;   // 40000
    const int E = in_sizes[1] / 2;     // 640000

    // One-time host resources (created on the pre-capture correctness call;
    // record/wait below become graph dependencies during capture).
    static cudaStream_t s_gemm = nullptr;
    static cudaEvent_t  ev_init = nullptr, ev_gemm = nullptr;
    if (s_gemm == nullptr) {
        cudaStreamCreateWithFlags(&s_gemm, cudaStreamNonBlocking);
        cudaEventCreateWithFlags(&ev_init, cudaEventDisableTiming);
        cudaEventCreateWithFlags(&ev_gemm, cudaEventDisableTiming);
        cudaFuncSetAttribute(gemm_kernel,
                             cudaFuncAttributeMaxDynamicSharedMemorySize, SM_TOT);
    }

    // init -> fork: [gemm] on s_gemm  ||  [count -> scan -> scatter] on default
    // join -> agg
    init_kernel<<<(N + 255) / 256, 256>>>((const int*)ei, W, N);
    cudaEventRecord(ev_init, 0);
    cudaStreamWaitEvent(s_gemm, ev_init, 0);
    gemm_kernel<<<(N + 127) / 128, 512, SM_TOT, s_gemm>>>(x, N);
    cudaEventRecord(ev_gemm, s_gemm);

    count_kernel<<<(E + 255) / 256, 256>>>(ei, E, N);
    scan_kernel<<<(N + 1023) / 1024, 1024>>>(N);
    scatter_kernel<<<(E + 255) / 256, 256>>>(ei, E, N);

    cudaStreamWaitEvent(0, ev_gemm, 0);
    agg_kernel<<<(N * 32 + 255) / 256, 256>>>(b, out, N);
}

// round 13
// speedup vs baseline: 1.5553x; 1.0293x over previous
#include <cuda_runtime.h>
#include <cuda_bf16.h>
#include <cuda_fp16.h>
#include <cstdint>

// Problem shape: N=40000 nodes, F_in=256, F_out=128, E=640000 edges.
static constexpr int MAXN = 40000;
static constexpr int MAXE = 640000;

// Scratch (allocation-free rule: __device__ globals)
__device__ int    g_is64;               // 1 if edge_index is int64, 0 if int32
__device__ __align__(16) int g_cnt[MAXN];   // in-degree histogram
__device__ int    g_rowptr[MAXN + 1];   // CSR row pointers (by dst)
__device__ float  g_dinv[MAXN];         // rsqrt(deg+1)
__device__ int    g_srcid[MAXE];        // CSR column (source node) ids
__device__ unsigned g_sd[MAXE];         // packed (d<<16)|s per edge
__device__ unsigned g_pos[MAXE];        // slot within dst bucket per edge
__device__ unsigned long long g_state[64];  // decoupled-lookback scan state
__device__ __align__(16) __half g_xwh[MAXN * 128];  // fp16 raw (x@W)[i] (UNSCALED)
// W^T image: [n=128][k=256] fp16
__device__ __align__(16) __half g_wh[128 * 256];

// ---------------------------------------------------------------------------
__device__ __forceinline__ uint32_t smem_u32(const void* p) {
    uint32_t a;
    asm("{ .reg .u64 t; cvta.to.shared.u64 t, %1; cvt.u32.u64 %0, t; }" : "=r"(a) : "l"(p));
    return a;
}
#define LDSM_X4(r0, r1, r2, r3, adr)                                              \
    asm volatile("ldmatrix.sync.aligned.m8n8.x4.shared.b16 {%0,%1,%2,%3}, [%4];"  \
                 : "=r"(r0), "=r"(r1), "=r"(r2), "=r"(r3) : "r"(adr))
#define MMA_F16(c, a, b)                                                          \
    asm volatile("mma.sync.aligned.m16n8k16.row.col.f32.f16.f16.f32 "             \
                 "{%0,%1,%2,%3}, {%4,%5,%6,%7}, {%8,%9}, {%0,%1,%2,%3};"          \
                 : "+f"((c)[0]), "+f"((c)[1]), "+f"((c)[2]), "+f"((c)[3])         \
                 : "r"((a)[0]), "r"((a)[1]), "r"((a)[2]), "r"((a)[3]),            \
                   "r"((b)[0]), "r"((b)[1]))

// ---------------------------------------------------------------------------
// 1) init: zero counters + scan state; block 0 probes index dtype; first
//    32768 threads build the W^T fp16 image.
__global__ void init_kernel(const int* __restrict__ ei32,
                            const float* __restrict__ W, int N) {
    int i = blockIdx.x * blockDim.x + threadIdx.x;
    if (i < N) g_cnt[i] = 0;
    if (i < 64) g_state[i] = 0ULL;
    if (i < 128 * 256) {
        int k = i & 255;
        int n = i >> 8;
        g_wh[n * 256 + k] = __float2half_rn(W[(size_t)k * 128 + n]);
    }
    if (blockIdx.x == 0) {
        __shared__ int red[8];
        int tid = threadIdx.x;
        int acc = 0;
        for (int k = tid; k < 1024; k += 256)
            acc |= ei32[2 * k + 1];              // int64 high halves
        #pragma unroll
        for (int off = 16; off > 0; off >>= 1)
            acc |= __shfl_down_sync(0xFFFFFFFFu, acc, off);
        if ((tid & 31) == 0) red[tid >> 5] = acc;
        __syncthreads();
        if (tid == 0) {
            int r = 0;
            #pragma unroll
            for (int w = 0; w < 8; w++) r |= red[w];
            g_is64 = (r == 0) ? 1 : 0;
        }
    }
}

__device__ __forceinline__ int load_idx(const void* ei, long long i, int is64) {
    if (is64) return (int)((const long long*)ei)[i];
    return ((const int*)ei)[i];
}

// 2) histogram of dst + record packed (d,s) and bucket slot per edge
__global__ void count_kernel(const void* __restrict__ ei, int E, int N) {
    int e = blockIdx.x * blockDim.x + threadIdx.x;
    if (e < E) {
        int is64 = g_is64;
        unsigned d = (unsigned)load_idx(ei, (long long)E + e, is64);
        unsigned s = (unsigned)load_idx(ei, e, is64);
        if (d < (unsigned)N && s < (unsigned)N) {
            unsigned pos = (unsigned)atomicAdd(&g_cnt[d], 1);
            g_pos[e] = pos;
            g_sd[e]  = (d << 16) | s;            // both < 65536
        } else {
            g_sd[e] = 0xFFFFFFFFu;               // sentinel: d=65535 >= N -> skip
        }
    }
}

// 3) multi-block exclusive scan, warp-parallel decoupled lookback; fused dinv.
//    1024 threads/block, 1 element/thread, grid = ceil(N/1024) (<= 64 blocks).
__global__ void __launch_bounds__(1024) scan_kernel(int N) {
    __shared__ int shw[32];
    __shared__ long long sh_excl;
    const int tid  = threadIdx.x;
    const int lane = tid & 31;
    const int warp = tid >> 5;
    const int b    = blockIdx.x;
    const int i    = b * 1024 + tid;

    int v = (i < N) ? g_cnt[i] : 0;
    if (i < N) g_dinv[i] = rsqrtf((float)v + 1.0f);

    // block-local inclusive scan
    int s = v;
    #pragma unroll
    for (int off = 1; off < 32; off <<= 1) {
        int t = __shfl_up_sync(0xFFFFFFFFu, s, off);
        if (lane >= off) s += t;
    }
    if (lane == 31) shw[warp] = s;
    __syncthreads();
    if (warp == 0) {
        int ws = shw[lane];
        #pragma unroll
        for (int off = 1; off < 32; off <<= 1) {
            int t = __shfl_up_sync(0xFFFFFFFFu, ws, off);
            if (lane >= off) ws += t;
        }
        shw[lane] = ws;
    }
    __syncthreads();
    const int incl  = s + (warp > 0 ? shw[warp - 1] : 0);
    const int total = shw[31];

    // warp-parallel decoupled lookback (warp 0)
    if (warp == 0) {
        if (b == 0) {
            if (lane == 0) {
                atomicExch(&g_state[0],
                           (2ULL << 32) | (unsigned long long)(unsigned)total);
                sh_excl = 0;
            }
        } else {
            if (lane == 0)
                atomicExch(&g_state[b],
                           (1ULL << 32) | (unsigned long long)(unsigned)total);
            __syncwarp();
            long long excl = 0;
            int p = b - 1;
            for (;;) {
                int idx = p - lane;               // lane 0 = nearest predecessor
                bool valid = (idx >= 0);
                unsigned long long st = 0;
                if (valid) {
                    do { st = atomicAdd(&g_state[idx], 0ULL); }
                    while ((st >> 32) == 0ULL);
                }
                unsigned mask2 = __ballot_sync(0xFFFFFFFFu,
                                               valid && (st >> 32) == 2ULL);
                int stop = mask2 ? (__ffs(mask2) - 1) : 32;   // nearest prefix lane
                long long contrib = (valid && lane <= stop)
                                    ? (long long)(st & 0xFFFFFFFFULL) : 0;
                #pragma unroll
                for (int off = 16; off > 0; off >>= 1)
                    contrib += __shfl_down_sync(0xFFFFFFFFu, contrib, off);
                contrib = __shfl_sync(0xFFFFFFFFu, contrib, 0);
                excl += contrib;
                if (mask2) break;                 // found a prefix; done
                p -= 32;                          // move window back
            }
            if (lane == 0) {
                atomicExch(&g_state[b],
                           (2ULL << 32) | (unsigned long long)(unsigned)(excl + total));
                sh_excl = excl;
            }
        }
    }
    __syncthreads();
    const long long excl = (b == 0) ? 0 : sh_excl;

    if (i < N) g_rowptr[i + 1] = (int)(excl + incl);
    if (i == 0) g_rowptr[0] = 0;
}

// 4) scatter (atomic-free): srcid[rowptr[d] + pos] = s
__global__ void scatter_kernel(int E, int N) {
    int e = blockIdx.x * blockDim.x + threadIdx.x;
    if (e < E) {
        unsigned sd = g_sd[e];
        unsigned d  = sd >> 16;
        if (d < (unsigned)N) {
            unsigned s = sd & 0xFFFFu;
            g_srcid[g_rowptr[d] + g_pos[e]] = (int)s;
        }
    }
}

// ---------------------------------------------------------------------------
// 5) GEMM via mma.sync fp16: xwh[i,:] = fp16( x[i,:] @ W )   (raw, no dinv)
//    CTA 128Mx128N, 16 warps (4Mx4N), warp 32Mx32N; K chunks of 64.
static constexpr int SM_AH  = 0;
static constexpr int SM_BH  = 18432;
static constexpr int SM_TOT = 36864;

__global__ void __launch_bounds__(512, 2)
gemm_kernel(const float* __restrict__ x, int N) {
    extern __shared__ unsigned char smc[];
    const uint32_t sm = smem_u32(smc);
    const int tid  = threadIdx.x;
    const int lane = tid & 31;
    const int wid  = tid >> 5;
    const int wm   = wid >> 2;          // 0..3 -> M offset wm*32
    const int wn   = wid & 3;           // 0..3 -> N offset wn*32
    const int row0 = blockIdx.x * 128;

    const float4* X4 = (const float4*)x;          // row stride 64 float4
    const uint4*  WH = (const uint4*)g_wh;        // row = 32 uint4

    float acc[2][4][4];
    #pragma unroll
    for (int t = 0; t < 2; t++)
        #pragma unroll
        for (int nt = 0; nt < 4; nt++)
            #pragma unroll
            for (int j = 0; j < 4; j++) acc[t][nt][j] = 0.f;

    const int m = tid >> 2;             // producer row 0..127
    const int h = tid & 3;              // k-quarter (16 floats) within chunk
    const int rr = min(row0 + m, N - 1);

    const uint32_t a_adr0 = sm + SM_AH + (wm * 32 + 0  + (lane & 15)) * 144 + ((lane >> 4) << 4);
    const uint32_t a_adr1 = sm + SM_AH + (wm * 32 + 16 + (lane & 15)) * 144 + ((lane >> 4) << 4);
    const uint32_t b_row  = (uint32_t)(wn * 32 + ((lane >> 4) << 3) + (lane & 7));
    const uint32_t b_koff = (uint32_t)(((lane >> 3) & 1) << 4);
    const uint32_t b_adr  = sm + SM_BH + b_row * 144 + b_koff;

    for (int c = 0; c < 4; c++) {
        if (c > 0) __syncthreads();     // previous compute done before overwrite
        // ---- A: load 4 float4 -> fp16 -> STS (2x uint4) ----
        #pragma unroll
        for (int p = 0; p < 2; p++) {
            float4 f0 = X4[(size_t)rr * 64 + c * 16 + h * 4 + p * 2];
            float4 f1 = X4[(size_t)rr * 64 + c * 16 + h * 4 + p * 2 + 1];
            __half2 h0 = __floats2half2_rn(f0.x, f0.y);
            __half2 h1 = __floats2half2_rn(f0.z, f0.w);
            __half2 h2 = __floats2half2_rn(f1.x, f1.y);
            __half2 h3 = __floats2half2_rn(f1.z, f1.w);
            uint32_t off = (uint32_t)(m * 144 + h * 32 + p * 16);
            *(uint4*)(smc + SM_AH + off) = make_uint4(
                *(uint32_t*)&h0, *(uint32_t*)&h1, *(uint32_t*)&h2, *(uint32_t*)&h3);
        }
        // ---- B chunk copy, 2 uint4 per thread (L2-resident) ----
        {
            int n   = tid >> 2;
            int kq  = (tid & 3) * 2;
            uint32_t dst = (uint32_t)(n * 144 + kq * 16);
            uint4 v0 = WH[n * 32 + c * 8 + kq];
            uint4 v1 = WH[n * 32 + c * 8 + kq + 1];
            *(uint4*)(smc + SM_BH + dst)      = v0;
            *(uint4*)(smc + SM_BH + dst + 16) = v1;
        }
        __syncthreads();

        // ---- compute: 4 k16 steps, single MMA term ----
        #pragma unroll
        for (int ks = 0; ks < 4; ks++) {
            uint32_t ah0[4], ah1[4];
            LDSM_X4(ah0[0], ah0[1], ah0[2], ah0[3], a_adr0 + ks * 32);
            LDSM_X4(ah1[0], ah1[1], ah1[2], ah1[3], a_adr1 + ks * 32);
            #pragma unroll
            for (int j = 0; j < 2; j++) {      // 2 n16-groups
                uint32_t bh[4];
                LDSM_X4(bh[0], bh[1], bh[2], bh[3], b_adr + j * 16 * 144 + ks * 32);
                MMA_F16(acc[0][2 * j],     ah0, bh);
                MMA_F16(acc[1][2 * j],     ah1, bh);
                MMA_F16(acc[0][2 * j + 1], ah0, bh + 2);
                MMA_F16(acc[1][2 * j + 1], ah1, bh + 2);
            }
        }
    }

    // ---- epilogue: write raw fp16 xwh (dinv applied in agg) ----
    uint32_t* xw = (uint32_t*)g_xwh;            // row stride 64 uint (half2)
    const int nb2 = wn * 16;                    // half2-base
    #pragma unroll
    for (int t = 0; t < 2; t++) {
        int r_lo = row0 + wm * 32 + t * 16 + (lane >> 2);
        int r_hi = r_lo + 8;
        #pragma unroll
        for (int nt = 0; nt < 4; nt++) {
            int ci = nb2 + nt * 4 + (lane & 3);
            if (r_lo < N) {
                __half2 p = __floats2half2_rn(acc[t][nt][0], acc[t][nt][1]);
                xw[(size_t)r_lo * 64 + ci] = *(uint32_t*)&p;
            }
            if (r_hi < N) {
                __half2 p = __floats2half2_rn(acc[t][nt][2], acc[t][nt][3]);
                xw[(size_t)r_hi * 64 + ci] = *(uint32_t*)&p;
            }
        }
    }
}

// ---------------------------------------------------------------------------
__device__ __forceinline__ void fma_h4(float4& a, uint2 u, float s) {
    float2 f0 = __half22float2(*(__half2*)&u.x);
    float2 f1 = __half22float2(*(__half2*)&u.y);
    a.x = fmaf(s, f0.x, a.x); a.y = fmaf(s, f0.y, a.y);
    a.z = fmaf(s, f1.x, a.z); a.w = fmaf(s, f1.y, a.w);
}

// 6) aggregation: one warp per node; per-source dinv folded in here.
//    out[i] = relu( dinv_i * ( dinv_i*xw_i + sum_e dinv_s*xw_s ) + b )
__global__ void __launch_bounds__(256) agg_kernel(const float* __restrict__ b,
                                                  float* __restrict__ out, int N) {
    int warp = (blockIdx.x * blockDim.x + threadIdx.x) >> 5;
    int lane = threadIdx.x & 31;
    if (warp >= N) return;
    int node = warp;

    const uint2* xw = (const uint2*)g_xwh;      // row stride 32 uint2
    float di = g_dinv[node];
    float4 acc = make_float4(0.f, 0.f, 0.f, 0.f);
    fma_h4(acc, xw[(size_t)node * 32 + lane], di);   // self-loop
    float4 bb = ((const float4*)b)[lane];

    int e   = g_rowptr[node];
    int end = g_rowptr[node + 1];
    for (; e + 8 <= end; e += 8) {
        int s[8]; float ds[8]; uint2 u[8];
        #pragma unroll
        for (int q = 0; q < 8; q++) s[q] = g_srcid[e + q];
        #pragma unroll
        for (int q = 0; q < 8; q++) {
            ds[q] = g_dinv[s[q]];
            u[q]  = xw[(size_t)s[q] * 32 + lane];
        }
        #pragma unroll
        for (int q = 0; q < 8; q++) fma_h4(acc, u[q], ds[q]);
    }
    if (e + 4 <= end) {
        int s[4]; float ds[4]; uint2 u[4];
        #pragma unroll
        for (int q = 0; q < 4; q++) s[q] = g_srcid[e + q];
        #pragma unroll
        for (int q = 0; q < 4; q++) {
            ds[q] = g_dinv[s[q]];
            u[q]  = xw[(size_t)s[q] * 32 + lane];
        }
        #pragma unroll
        for (int q = 0; q < 4; q++) fma_h4(acc, u[q], ds[q]);
        e += 4;
    }
    for (; e < end; e++) {
        int s = g_srcid[e];
        fma_h4(acc, xw[(size_t)s * 32 + lane], g_dinv[s]);
    }

    float4 o;
    o.x = fmaxf(fmaf(di, acc.x, bb.x), 0.f);
    o.y = fmaxf(fmaf(di, acc.y, bb.y), 0.f);
    o.z = fmaxf(fmaf(di, acc.z, bb.z), 0.f);
    o.w = fmaxf(fmaf(di, acc.w, bb.w), 0.f);
    ((float4*)out)[(size_t)node * 32 + lane] = o;
}

// ---------------------------------------------------------------------------
extern "C" void kernel_launch(void* const* d_in, const int* in_sizes, int n_in,
                              void* d_out, int out_size) {
    const float* x  = (const float*)d_in[0];
    const void*  ei = d_in[1];                 // [2, E] int32 or int64 (probed)
    const float* W  = (const float*)d_in[2];
    const float* b  = (const float*)d_in[3];
    float*       out = (float*)d_out;

    const int N = in_sizes[0] / 256;   // 40000
    const int E = in_sizes[1] / 2;     // 640000

    // One-time host resources (created on the pre-capture correctness call;
    // record/wait below become graph dependencies during capture).
    static cudaStream_t s_gemm = nullptr;
    static cudaEvent_t  ev_init = nullptr, ev_gemm = nullptr;
    if (s_gemm == nullptr) {
        cudaStreamCreateWithFlags(&s_gemm, cudaStreamNonBlocking);
        cudaEventCreateWithFlags(&ev_init, cudaEventDisableTiming);
        cudaEventCreateWithFlags(&ev_gemm, cudaEventDisableTiming);
        cudaFuncSetAttribute(gemm_kernel,
                             cudaFuncAttributeMaxDynamicSharedMemorySize, SM_TOT);
    }

    // init -> fork: [gemm] on s_gemm  ||  [count -> scan -> scatter] on default
    // join -> agg
    init_kernel<<<(N + 255) / 256, 256>>>((const int*)ei, W, N);
    cudaEventRecord(ev_init, 0);
    cudaStreamWaitEvent(s_gemm, ev_init, 0);
    gemm_kernel<<<(N + 127) / 128, 512, SM_TOT, s_gemm>>>(x, N);
    cudaEventRecord(ev_gemm, s_gemm);

    count_kernel<<<(E + 255) / 256, 256>>>(ei, E, N);
    scan_kernel<<<(N + 1023) / 1024, 1024>>>(N);
    scatter_kernel<<<(E + 255) / 256, 256>>>(E, N);

    cudaStreamWaitEvent(0, ev_gemm, 0);
    agg_kernel<<<(N * 32 + 255) / 256, 256>>>(b, out, N);
}

// round 14
// speedup vs baseline: 1.5610x; 1.0036x over previous
#include <cuda_runtime.h>
#include <cuda_bf16.h>
#include <cuda_fp16.h>
#include <cstdint>

// Problem shape: N=40000 nodes, F_in=256, F_out=128, E=640000 edges.
static constexpr int MAXN = 40000;
static constexpr int MAXE = 640000;

// Scratch (allocation-free rule: __device__ globals)
__device__ int    g_is64;               // 1 if edge_index is int64, 0 if int32
__device__ __align__(16) int g_cnt[MAXN];   // in-degree histogram
__device__ int    g_rowptr[MAXN + 1];   // CSR row pointers (by dst)
__device__ float  g_dinv[MAXN];         // rsqrt(deg+1)
__device__ int    g_srcid[MAXE];        // CSR column (source node) ids
__device__ unsigned g_sd[MAXE];         // packed (d<<16)|s per edge
__device__ unsigned g_pos[MAXE];        // slot within dst bucket per edge
__device__ unsigned long long g_state[64];  // decoupled-lookback scan state
__device__ __align__(16) __half g_xwh[MAXN * 128];  // fp16 raw (x@W)[i] (UNSCALED)
// W^T image: [n=128][k=256] fp16
__device__ __align__(16) __half g_wh[128 * 256];

// ---------------------------------------------------------------------------
__device__ __forceinline__ uint32_t smem_u32(const void* p) {
    uint32_t a;
    asm("{ .reg .u64 t; cvta.to.shared.u64 t, %1; cvt.u32.u64 %0, t; }" : "=r"(a) : "l"(p));
    return a;
}
#define LDSM_X4(r0, r1, r2, r3, adr)                                              \
    asm volatile("ldmatrix.sync.aligned.m8n8.x4.shared.b16 {%0,%1,%2,%3}, [%4];"  \
                 : "=r"(r0), "=r"(r1), "=r"(r2), "=r"(r3) : "r"(adr))
#define MMA_F16(c, a, b)                                                          \
    asm volatile("mma.sync.aligned.m16n8k16.row.col.f32.f16.f16.f32 "             \
                 "{%0,%1,%2,%3}, {%4,%5,%6,%7}, {%8,%9}, {%0,%1,%2,%3};"          \
                 : "+f"((c)[0]), "+f"((c)[1]), "+f"((c)[2]), "+f"((c)[3])         \
                 : "r"((a)[0]), "r"((a)[1]), "r"((a)[2]), "r"((a)[3]),            \
                   "r"((b)[0]), "r"((b)[1]))

// ---------------------------------------------------------------------------
// 1) init: zero counters + scan state; block 0 probes index dtype; first
//    32768 threads build the W^T fp16 image.
__global__ void init_kernel(const int* __restrict__ ei32,
                            const float* __restrict__ W, int N) {
    int i = blockIdx.x * blockDim.x + threadIdx.x;
    if (i < N) g_cnt[i] = 0;
    if (i < 64) g_state[i] = 0ULL;
    if (i < 128 * 256) {
        int k = i & 255;
        int n = i >> 8;
        g_wh[n * 256 + k] = __float2half_rn(W[(size_t)k * 128 + n]);
    }
    if (blockIdx.x == 0) {
        __shared__ int red[8];
        int tid = threadIdx.x;
        int acc = 0;
        for (int k = tid; k < 1024; k += 256)
            acc |= ei32[2 * k + 1];              // int64 high halves
        #pragma unroll
        for (int off = 16; off > 0; off >>= 1)
            acc |= __shfl_down_sync(0xFFFFFFFFu, acc, off);
        if ((tid & 31) == 0) red[tid >> 5] = acc;
        __syncthreads();
        if (tid == 0) {
            int r = 0;
            #pragma unroll
            for (int w = 0; w < 8; w++) r |= red[w];
            g_is64 = (r == 0) ? 1 : 0;
        }
    }
}

__device__ __forceinline__ int load_idx(const void* ei, long long i, int is64) {
    if (is64) return (int)((const long long*)ei)[i];
    return ((const int*)ei)[i];
}

// 2) histogram of dst + record packed (d,s) and bucket slot per edge
__global__ void count_kernel(const void* __restrict__ ei, int E, int N) {
    int e = blockIdx.x * blockDim.x + threadIdx.x;
    if (e < E) {
        int is64 = g_is64;
        unsigned d = (unsigned)load_idx(ei, (long long)E + e, is64);
        unsigned s = (unsigned)load_idx(ei, e, is64);
        if (d < (unsigned)N && s < (unsigned)N) {
            unsigned pos = (unsigned)atomicAdd(&g_cnt[d], 1);
            g_pos[e] = pos;
            g_sd[e]  = (d << 16) | s;            // both < 65536
        } else {
            g_sd[e] = 0xFFFFFFFFu;               // sentinel: d=65535 >= N -> skip
        }
    }
}

// 3) multi-block exclusive scan, warp-parallel decoupled lookback; fused dinv.
__global__ void __launch_bounds__(1024) scan_kernel(int N) {
    __shared__ int shw[32];
    __shared__ long long sh_excl;
    const int tid  = threadIdx.x;
    const int lane = tid & 31;
    const int warp = tid >> 5;
    const int b    = blockIdx.x;
    const int i    = b * 1024 + tid;

    int v = (i < N) ? g_cnt[i] : 0;
    if (i < N) g_dinv[i] = rsqrtf((float)v + 1.0f);

    // block-local inclusive scan
    int s = v;
    #pragma unroll
    for (int off = 1; off < 32; off <<= 1) {
        int t = __shfl_up_sync(0xFFFFFFFFu, s, off);
        if (lane >= off) s += t;
    }
    if (lane == 31) shw[warp] = s;
    __syncthreads();
    if (warp == 0) {
        int ws = shw[lane];
        #pragma unroll
        for (int off = 1; off < 32; off <<= 1) {
            int t = __shfl_up_sync(0xFFFFFFFFu, ws, off);
            if (lane >= off) ws += t;
        }
        shw[lane] = ws;
    }
    __syncthreads();
    const int incl  = s + (warp > 0 ? shw[warp - 1] : 0);
    const int total = shw[31];

    // warp-parallel decoupled lookback (warp 0)
    if (warp == 0) {
        if (b == 0) {
            if (lane == 0) {
                atomicExch(&g_state[0],
                           (2ULL << 32) | (unsigned long long)(unsigned)total);
                sh_excl = 0;
            }
        } else {
            if (lane == 0)
                atomicExch(&g_state[b],
                           (1ULL << 32) | (unsigned long long)(unsigned)total);
            __syncwarp();
            long long excl = 0;
            int p = b - 1;
            for (;;) {
                int idx = p - lane;               // lane 0 = nearest predecessor
                bool valid = (idx >= 0);
                unsigned long long st = 0;
                if (valid) {
                    do { st = atomicAdd(&g_state[idx], 0ULL); }
                    while ((st >> 32) == 0ULL);
                }
                unsigned mask2 = __ballot_sync(0xFFFFFFFFu,
                                               valid && (st >> 32) == 2ULL);
                int stop = mask2 ? (__ffs(mask2) - 1) : 32;   // nearest prefix lane
                long long contrib = (valid && lane <= stop)
                                    ? (long long)(st & 0xFFFFFFFFULL) : 0;
                #pragma unroll
                for (int off = 16; off > 0; off >>= 1)
                    contrib += __shfl_down_sync(0xFFFFFFFFu, contrib, off);
                contrib = __shfl_sync(0xFFFFFFFFu, contrib, 0);
                excl += contrib;
                if (mask2) break;                 // found a prefix; done
                p -= 32;                          // move window back
            }
            if (lane == 0) {
                atomicExch(&g_state[b],
                           (2ULL << 32) | (unsigned long long)(unsigned)(excl + total));
                sh_excl = excl;
            }
        }
    }
    __syncthreads();
    const long long excl = (b == 0) ? 0 : sh_excl;

    if (i < N) g_rowptr[i + 1] = (int)(excl + incl);
    if (i == 0) g_rowptr[0] = 0;
}

// 4) scatter (atomic-free): srcid[rowptr[d] + pos] = s
__global__ void scatter_kernel(int E, int N) {
    int e = blockIdx.x * blockDim.x + threadIdx.x;
    if (e < E) {
        unsigned sd = g_sd[e];
        unsigned d  = sd >> 16;
        if (d < (unsigned)N) {
            unsigned s = sd & 0xFFFFu;
            g_srcid[g_rowptr[d] + g_pos[e]] = (int)s;
        }
    }
}

// ---------------------------------------------------------------------------
// 5) GEMM via mma.sync fp16: xwh[i,:] = fp16( x[i,:] @ W )   (raw, no dinv)
//    CTA 64Mx128N, 8 warps (2Mx4N), warp 32Mx32N; K chunks of 64.
//    256 threads, 4 CTAs/SM: sibling CTAs overlap load and MMA phases.
static constexpr int SM_AH  = 0;                  // 64 * 144 = 9216 B
static constexpr int SM_BH  = 9216;               // 128 * 144 = 18432 B
static constexpr int SM_TOT = 27648;

__global__ void __launch_bounds__(256, 4)
gemm_kernel(const float* __restrict__ x, int N) {
    extern __shared__ unsigned char smc[];
    const uint32_t sm = smem_u32(smc);
    const int tid  = threadIdx.x;
    const int lane = tid & 31;
    const int wid  = tid >> 5;
    const int wm   = wid >> 2;          // 0..1 -> M offset wm*32
    const int wn   = wid & 3;           // 0..3 -> N offset wn*32
    const int row0 = blockIdx.x * 64;

    const float4* X4 = (const float4*)x;          // row stride 64 float4
    const uint4*  WH = (const uint4*)g_wh;        // row = 32 uint4

    float acc[2][4][4];
    #pragma unroll
    for (int t = 0; t < 2; t++)
        #pragma unroll
        for (int nt = 0; nt < 4; nt++)
            #pragma unroll
            for (int j = 0; j < 4; j++) acc[t][nt][j] = 0.f;

    const int m = tid >> 2;             // producer row 0..63
    const int h = tid & 3;              // k-quarter (16 floats) within chunk
    const int rr = min(row0 + m, N - 1);

    const uint32_t a_adr0 = sm + SM_AH + (wm * 32 + 0  + (lane & 15)) * 144 + ((lane >> 4) << 4);
    const uint32_t a_adr1 = sm + SM_AH + (wm * 32 + 16 + (lane & 15)) * 144 + ((lane >> 4) << 4);
    const uint32_t b_row  = (uint32_t)(wn * 32 + ((lane >> 4) << 3) + (lane & 7));
    const uint32_t b_koff = (uint32_t)(((lane >> 3) & 1) << 4);
    const uint32_t b_adr  = sm + SM_BH + b_row * 144 + b_koff;

    for (int c = 0; c < 4; c++) {
        if (c > 0) __syncthreads();     // previous compute done before overwrite
        // ---- A: load 4 float4 -> fp16 -> STS (2x uint4) ----
        #pragma unroll
        for (int p = 0; p < 2; p++) {
            float4 f0 = X4[(size_t)rr * 64 + c * 16 + h * 4 + p * 2];
            float4 f1 = X4[(size_t)rr * 64 + c * 16 + h * 4 + p * 2 + 1];
            __half2 h0 = __floats2half2_rn(f0.x, f0.y);
            __half2 h1 = __floats2half2_rn(f0.z, f0.w);
            __half2 h2 = __floats2half2_rn(f1.x, f1.y);
            __half2 h3 = __floats2half2_rn(f1.z, f1.w);
            uint32_t off = (uint32_t)(m * 144 + h * 32 + p * 16);
            *(uint4*)(smc + SM_AH + off) = make_uint4(
                *(uint32_t*)&h0, *(uint32_t*)&h1, *(uint32_t*)&h2, *(uint32_t*)&h3);
        }
        // ---- B chunk copy, 4 uint4 per thread (L2-resident) ----
        #pragma unroll
        for (int it = 0; it < 4; it++) {
            int idx = tid + it * 256;          // 0..1023
            int n   = idx >> 3;
            int kq  = idx & 7;
            uint32_t dst = (uint32_t)(n * 144 + kq * 16);
            *(uint4*)(smc + SM_BH + dst) = WH[n * 32 + c * 8 + kq];
        }
        __syncthreads();

        // ---- compute: 4 k16 steps, single MMA term ----
        #pragma unroll
        for (int ks = 0; ks < 4; ks++) {
            uint32_t ah0[4], ah1[4];
            LDSM_X4(ah0[0], ah0[1], ah0[2], ah0[3], a_adr0 + ks * 32);
            LDSM_X4(ah1[0], ah1[1], ah1[2], ah1[3], a_adr1 + ks * 32);
            #pragma unroll
            for (int j = 0; j < 2; j++) {      // 2 n16-groups
                uint32_t bh[4];
                LDSM_X4(bh[0], bh[1], bh[2], bh[3], b_adr + j * 16 * 144 + ks * 32);
                MMA_F16(acc[0][2 * j],     ah0, bh);
                MMA_F16(acc[1][2 * j],     ah1, bh);
                MMA_F16(acc[0][2 * j + 1], ah0, bh + 2);
                MMA_F16(acc[1][2 * j + 1], ah1, bh + 2);
            }
        }
    }

    // ---- epilogue: write raw fp16 xwh (dinv applied in agg) ----
    uint32_t* xw = (uint32_t*)g_xwh;            // row stride 64 uint (half2)
    const int nb2 = wn * 16;                    // half2-base
    #pragma unroll
    for (int t = 0; t < 2; t++) {
        int r_lo = row0 + wm * 32 + t * 16 + (lane >> 2);
        int r_hi = r_lo + 8;
        #pragma unroll
        for (int nt = 0; nt < 4; nt++) {
            int ci = nb2 + nt * 4 + (lane & 3);
            if (r_lo < N) {
                __half2 p = __floats2half2_rn(acc[t][nt][0], acc[t][nt][1]);
                xw[(size_t)r_lo * 64 + ci] = *(uint32_t*)&p;
            }
            if (r_hi < N) {
                __half2 p = __floats2half2_rn(acc[t][nt][2], acc[t][nt][3]);
                xw[(size_t)r_hi * 64 + ci] = *(uint32_t*)&p;
            }
        }
    }
}

// ---------------------------------------------------------------------------
__device__ __forceinline__ void fma_h4(float4& a, uint2 u, float s) {
    float2 f0 = __half22float2(*(__half2*)&u.x);
    float2 f1 = __half22float2(*(__half2*)&u.y);
    a.x = fmaf(s, f0.x, a.x); a.y = fmaf(s, f0.y, a.y);
    a.z = fmaf(s, f1.x, a.z); a.w = fmaf(s, f1.y, a.w);
}

// 6) aggregation: one warp per node; per-source dinv folded in here.
//    out[i] = relu( dinv_i * ( dinv_i*xw_i + sum_e dinv_s*xw_s ) + b )
__global__ void __launch_bounds__(256) agg_kernel(const float* __restrict__ b,
                                                  float* __restrict__ out, int N) {
    int warp = (blockIdx.x * blockDim.x + threadIdx.x) >> 5;
    int lane = threadIdx.x & 31;
    if (warp >= N) return;
    int node = warp;

    const uint2* xw = (const uint2*)g_xwh;      // row stride 32 uint2
    float di = g_dinv[node];
    float4 acc = make_float4(0.f, 0.f, 0.f, 0.f);
    fma_h4(acc, xw[(size_t)node * 32 + lane], di);   // self-loop
    float4 bb = ((const float4*)b)[lane];

    int e   = g_rowptr[node];
    int end = g_rowptr[node + 1];
    for (; e + 8 <= end; e += 8) {
        int s[8]; float ds[8]; uint2 u[8];
        #pragma unroll
        for (int q = 0; q < 8; q++) s[q] = g_srcid[e + q];
        #pragma unroll
        for (int q = 0; q < 8; q++) {
            ds[q] = g_dinv[s[q]];
            u[q]  = xw[(size_t)s[q] * 32 + lane];
        }
        #pragma unroll
        for (int q = 0; q < 8; q++) fma_h4(acc, u[q], ds[q]);
    }
    if (e + 4 <= end) {
        int s[4]; float ds[4]; uint2 u[4];
        #pragma unroll
        for (int q = 0; q < 4; q++) s[q] = g_srcid[e + q];
        #pragma unroll
        for (int q = 0; q < 4; q++) {
            ds[q] = g_dinv[s[q]];
            u[q]  = xw[(size_t)s[q] * 32 + lane];
        }
        #pragma unroll
        for (int q = 0; q < 4; q++) fma_h4(acc, u[q], ds[q]);
        e += 4;
    }
    for (; e < end; e++) {
        int s = g_srcid[e];
        fma_h4(acc, xw[(size_t)s * 32 + lane], g_dinv[s]);
    }

    float4 o;
    o.x = fmaxf(fmaf(di, acc.x, bb.x), 0.f);
    o.y = fmaxf(fmaf(di, acc.y, bb.y), 0.f);
    o.z = fmaxf(fmaf(di, acc.z, bb.z), 0.f);
    o.w = fmaxf(fmaf(di, acc.w, bb.w), 0.f);
    ((float4*)out)[(size_t)node * 32 + lane] = o;
}

// ---------------------------------------------------------------------------
extern "C" void kernel_launch(void* const* d_in, const int* in_sizes, int n_in,
                              void* d_out, int out_size) {
    const float* x  = (const float*)d_in[0];
    const void*  ei = d_in[1];                 // [2, E] int32 or int64 (probed)
    const float* W  = (const float*)d_in[2];
    const float* b  = (const float*)d_in[3];
    float*       out = (float*)d_out;

    const int N = in_sizes[0] / 256;   // 40000
    const int E = in_sizes[1] / 2;     // 640000

    // One-time host resources (created on the pre-capture correctness call;
    // record/wait below become graph dependencies during capture).
    static cudaStream_t s_gemm = nullptr;
    static cudaEvent_t  ev_init = nullptr, ev_gemm = nullptr;
    if (s_gemm == nullptr) {
        cudaStreamCreateWithFlags(&s_gemm, cudaStreamNonBlocking);
        cudaEventCreateWithFlags(&ev_init, cudaEventDisableTiming);
        cudaEventCreateWithFlags(&ev_gemm, cudaEventDisableTiming);
        cudaFuncSetAttribute(gemm_kernel,
                             cudaFuncAttributeMaxDynamicSharedMemorySize, SM_TOT);
    }

    // init -> fork: [gemm] on s_gemm  ||  [count -> scan -> scatter] on default
    // join -> agg
    init_kernel<<<(N + 255) / 256, 256>>>((const int*)ei, W, N);
    cudaEventRecord(ev_init, 0);
    cudaStreamWaitEvent(s_gemm, ev_init, 0);
    gemm_kernel<<<(N + 63) / 64, 256, SM_TOT, s_gemm>>>(x, N);
    cudaEventRecord(ev_gemm, s_gemm);

    count_kernel<<<(E + 255) / 256, 256>>>(ei, E, N);
    scan_kernel<<<(N + 1023) / 1024, 1024>>>(N);
    scatter_kernel<<<(E + 255) / 256, 256>>>(E, N);

    cudaStreamWaitEvent(0, ev_gemm, 0);
    agg_kernel<<<(N * 32 + 255) / 256, 256>>>(b, out, N);
}